// round 3
// baseline (speedup 1.0000x reference)
#include <cuda_runtime.h>
#include <cuda_bf16.h>
#include <math.h>

#define NN 100000
#define EE 1600000
#define HID 64
#define HEADS 4
#define GATD 256

// ---------------- device scratch (no allocations allowed) ----------------
__device__ int   g_is64;
__device__ int   g_count[NN];
__device__ int   g_rowptr[NN + 1];
__device__ int   g_cursor[NN];
__device__ int   g_blocksums[256];
__device__ float g_dinv[NN];
__device__ int   g_esrc[EE];
__device__ float g_enorm[EE];
__device__ float g_hlin[NN * HID];
__device__ float g_h[NN * HID];
__device__ float g_hg[NN * GATD];
__device__ float g_asrc[NN * HEADS];
__device__ float g_adst[NN * HEADS];
__device__ float g_hatt[NN * GATD];

// Read edge id #idx from the raw edge buffer, honoring detected dtype.
__device__ __forceinline__ int ld_edge(const void* ei, int is64, long long idx) {
    if (is64) return (int)((const long long*)ei)[idx];
    return ((const int*)ei)[idx];
}

// ---------------- dtype detection (int32 vs int64 edge_index) ----------------
__global__ void k_detect(const int* __restrict__ ei) {
    int all0 = 1;
    for (int i = 1; i < 32; i += 2)
        if (ei[i] != 0) { all0 = 0; break; }
    g_is64 = all0;
}

// ---------------- CSR build ----------------
__global__ void k_zero(int n) {
    int i = blockIdx.x * blockDim.x + threadIdx.x;
    if (i < n) g_count[i] = 0;
}

__global__ void k_count(const void* __restrict__ ei, int e) {
    int i = blockIdx.x * blockDim.x + threadIdx.x;
    if (i < e) {
        int is64 = g_is64;
        int d = ld_edge(ei, is64, (long long)e + i);
        atomicAdd(&g_count[d], 1);
    }
}

__global__ void k_scan1(int n) {
    __shared__ int s[512];
    int tid = threadIdx.x;
    int i = blockIdx.x * 512 + tid;
    int v = (i < n) ? g_count[i] : 0;
    s[tid] = v;
    __syncthreads();
    for (int off = 1; off < 512; off <<= 1) {
        int t = (tid >= off) ? s[tid - off] : 0;
        __syncthreads();
        s[tid] += t;
        __syncthreads();
    }
    if (i < n) g_rowptr[i] = s[tid] - v;  // exclusive
    if (tid == 511) g_blocksums[blockIdx.x] = s[511];
}

__global__ void k_scan2(int nb) {
    int run = 0;
    for (int b = 0; b < nb; ++b) {
        int t = g_blocksums[b];
        g_blocksums[b] = run;
        run += t;
    }
}

__global__ void k_scan3(int n, int e) {
    int i = blockIdx.x * blockDim.x + threadIdx.x;
    if (i < n) {
        int rp = g_rowptr[i] + g_blocksums[i >> 9];
        g_rowptr[i] = rp;
        g_cursor[i] = rp;
        g_dinv[i] = rsqrtf((float)(g_count[i] + 1));  // +1 for self loop
        if (i == 0) g_rowptr[n] = e;
    }
}

__global__ void k_scatter(const void* __restrict__ ei, int e) {
    int i = blockIdx.x * blockDim.x + threadIdx.x;
    if (i < e) {
        int is64 = g_is64;
        int s = ld_edge(ei, is64, i);
        int d = ld_edge(ei, is64, (long long)e + i);
        int p = atomicAdd(&g_cursor[d], 1);
        g_esrc[p] = s;
        g_enorm[p] = g_dinv[s] * g_dinv[d];
    }
}

// ---------------- small GEMM: hlin = SRC @ W  ([n,K] @ [K,64]) ----------------
// SRC==0: read from parameter X (true device pointer from harness).
// SRC==1: read from __device__ g_h (device-code reference — NEVER pass a
//         __device__ symbol as a host-side kernel argument: that passes the
//         host shadow, which GB300's ATS dereferences as zeros).
template <int K, int SRC>
__global__ void k_gemm_h(const float* __restrict__ X, const float* __restrict__ W, int n) {
    __shared__ float sx[4][K];
    int tid = threadIdx.x;
    int l = tid >> 6, col = tid & 63;
    int base = blockIdx.x * 4;
    const float* __restrict__ src = (SRC == 1) ? (const float*)g_h : X;
    for (int idx = tid; idx < 4 * K; idx += 256) {
        int r = base + idx / K;
        sx[idx / K][idx % K] = (r < n) ? src[r * K + (idx % K)] : 0.f;
    }
    __syncthreads();
    int node = base + l;
    if (node < n) {
        float acc = 0.f;
#pragma unroll
        for (int k = 0; k < K; ++k) acc += sx[l][k] * W[k * 64 + col];
        g_hlin[node * 64 + col] = acc;
    }
}

// ---------------- GCN aggregation: g_h = [res +] relu(agg + b) ----------------
__global__ void k_gcn_agg(const float* __restrict__ b, int n, int residual) {
    int tid = threadIdx.x;
    int l = tid >> 6, col = tid & 63;
    int node = blockIdx.x * 4 + l;
    if (node >= n) return;
    float di = g_dinv[node];
    float acc = di * di * g_hlin[node * 64 + col];  // self loop
    int beg = g_rowptr[node], end = g_rowptr[node + 1];
    int j = beg;
    for (; j + 1 < end; j += 2) {
        int s0 = g_esrc[j], s1 = g_esrc[j + 1];
        float w0 = g_enorm[j], w1 = g_enorm[j + 1];
        acc += w0 * g_hlin[s0 * 64 + col];
        acc += w1 * g_hlin[s1 * 64 + col];
    }
    if (j < end) acc += g_enorm[j] * g_hlin[g_esrc[j] * 64 + col];
    float v = fmaxf(acc + b[col], 0.f);
    g_h[node * 64 + col] = residual ? (g_h[node * 64 + col] + v) : v;
}

// ---------------- GAT linear + attention coefficients ----------------
__global__ void k_gat_gemm(const float* __restrict__ wg,
                           const float* __restrict__ att_s,
                           const float* __restrict__ att_d, int n) {
    __shared__ float sh[64];
    __shared__ float s_as[8], s_ad[8];
    int tid = threadIdx.x;
    int warp = tid >> 5, lane = tid & 31;
    float a_s = att_s[tid], a_d = att_d[tid];
    for (int nl = 0; nl < 8; ++nl) {
        int node = blockIdx.x * 8 + nl;
        if (node >= n) break;  // uniform over block
        __syncthreads();
        if (tid < 64) sh[tid] = g_h[node * 64 + tid];
        __syncthreads();
        float acc = 0.f;
#pragma unroll
        for (int k = 0; k < 64; ++k) acc += sh[k] * wg[k * 256 + tid];
        g_hg[node * 256 + tid] = acc;
        float vs = acc * a_s, vd = acc * a_d;
#pragma unroll
        for (int o = 16; o > 0; o >>= 1) {
            vs += __shfl_xor_sync(0xffffffffu, vs, o);
            vd += __shfl_xor_sync(0xffffffffu, vd, o);
        }
        if (lane == 0) { s_as[warp] = vs; s_ad[warp] = vd; }
        __syncthreads();
        if (tid < 4) {
            g_asrc[node * 4 + tid] = s_as[2 * tid] + s_as[2 * tid + 1];
            g_adst[node * 4 + tid] = s_ad[2 * tid] + s_ad[2 * tid + 1];
        }
    }
}

// ---------------- GAT softmax + aggregation (1 block of 256 per node) ----------------
__global__ void k_gat_agg(const float* __restrict__ bg, int n) {
    int i = blockIdx.x;
    int tid = threadIdx.x;
    int h = tid >> 6;   // head for my output column
    int hh = tid & 3;   // head I compute exp for in tiled phase
    __shared__ float s_adst[4];
    __shared__ float s_m[4];
    __shared__ float s_den[4];
    __shared__ float s_red[256];
    __shared__ float s_ex[256];
    __shared__ int   s_src[64];
    if (tid < 4) { s_adst[tid] = g_adst[i * 4 + tid]; s_den[tid] = 0.f; }
    __syncthreads();
    int beg = g_rowptr[i], end = g_rowptr[i + 1];
    int m = end - beg + 1;  // + self loop
    float ad_hh = s_adst[hh];
    // phase 1: per-head max of leaky_relu(a_src[s] + a_dst[i])
    float mx = -1e30f;
    for (int idx = tid; idx < m * 4; idx += 256) {
        int jj = idx >> 2;
        int s = (jj < m - 1) ? g_esrc[beg + jj] : i;
        float e = g_asrc[s * 4 + hh] + ad_hh;
        e = e > 0.f ? e : 0.2f * e;
        mx = fmaxf(mx, e);
    }
    s_red[tid] = mx;
    __syncthreads();
    if (tid < 4) {
        float v = -1e30f;
        for (int t = tid; t < 256; t += 4) v = fmaxf(v, s_red[t]);
        s_m[tid] = v;
    }
    __syncthreads();
    float m_hh = s_m[hh];
    float acc = 0.f;
    float den_part = 0.f;
    // phase 2: tiled exp + weighted accumulate
    for (int t0 = 0; t0 < m; t0 += 64) {
        int tcnt = min(64, m - t0);
        __syncthreads();  // protect s_src/s_ex reuse
        if (tid < tcnt) {
            int jj = t0 + tid;
            s_src[tid] = (jj < m - 1) ? g_esrc[beg + jj] : i;
        }
        __syncthreads();
        if (tid < tcnt * 4) {
            int jj = tid >> 2;
            int s = s_src[jj];
            float e = g_asrc[s * 4 + hh] + ad_hh;
            e = e > 0.f ? e : 0.2f * e;
            float ex = __expf(e - m_hh);
            s_ex[tid] = ex;
            den_part += ex;
        }
        __syncthreads();
        for (int jj = 0; jj < tcnt; ++jj) {
            acc += s_ex[jj * 4 + h] * g_hg[s_src[jj] * 256 + tid];
        }
    }
    atomicAdd(&s_den[hh], den_part);
    __syncthreads();
    float out = acc / (s_den[h] + 1e-16f) + bg[tid];
    g_hatt[i * 256 + tid] = out;
}

// ---------------- classifier: relu(hatt@wc1+bc1) @ wc2 + bc2, log_softmax ----------------
__global__ void k_classifier(const float* __restrict__ wc1, const float* __restrict__ bc1,
                             const float* __restrict__ wc2, const float* __restrict__ bc2,
                             float* __restrict__ out, int n) {
    __shared__ float s_in[4][256];
    __shared__ float s_z[4][64];
    __shared__ float s_lg[4][3];
    int tid = threadIdx.x;
    int l = tid >> 6, col = tid & 63;
    int base = blockIdx.x * 4;
    for (int idx = tid; idx < 1024; idx += 256) {
        int r = base + (idx >> 8);
        s_in[idx >> 8][idx & 255] = (r < n) ? g_hatt[r * 256 + (idx & 255)] : 0.f;
    }
    __syncthreads();
    float acc = bc1[col];
#pragma unroll 8
    for (int k = 0; k < 256; ++k) acc += s_in[l][k] * wc1[k * 64 + col];
    s_z[l][col] = fmaxf(acc, 0.f);
    __syncthreads();
    if (tid < 12) {
        int ll = tid / 3, o = tid % 3;
        float a = bc2[o];
#pragma unroll
        for (int k = 0; k < 64; ++k) a += s_z[ll][k] * wc2[k * 3 + o];
        s_lg[ll][o] = a;
    }
    __syncthreads();
    if (tid < 4) {
        int node = base + tid;
        if (node < n) {
            float l0 = s_lg[tid][0], l1 = s_lg[tid][1], l2 = s_lg[tid][2];
            float mm = fmaxf(l0, fmaxf(l1, l2));
            float lse = mm + logf(__expf(l0 - mm) + __expf(l1 - mm) + __expf(l2 - mm));
            out[node * 3 + 0] = l0 - lse;
            out[node * 3 + 1] = l1 - lse;
            out[node * 3 + 2] = l2 - lse;
        }
    }
}

// ---------------- launch ----------------
extern "C" void kernel_launch(void* const* d_in, const int* in_sizes, int n_in,
                              void* d_out, int out_size) {
    const float* x     = (const float*)d_in[0];
    const void*  ei    = (const void*)d_in[1];
    const float* w1    = (const float*)d_in[2];
    const float* b1    = (const float*)d_in[3];
    const float* w2    = (const float*)d_in[4];
    const float* b2    = (const float*)d_in[5];
    const float* w3    = (const float*)d_in[6];
    const float* b3    = (const float*)d_in[7];
    const float* wg    = (const float*)d_in[8];
    const float* bg    = (const float*)d_in[9];
    const float* att_s = (const float*)d_in[10];
    const float* att_d = (const float*)d_in[11];
    const float* wc1   = (const float*)d_in[12];
    const float* bc1   = (const float*)d_in[13];
    const float* wc2   = (const float*)d_in[14];
    const float* bc2   = (const float*)d_in[15];
    float* out = (float*)d_out;

    int n = in_sizes[0] / 8;   // N nodes (x is [N,8])
    int e = in_sizes[1] / 2;   // E edges (edge_index is [2,E])

    int nb512 = (n + 511) / 512;

    // dtype detection + CSR build
    k_detect<<<1, 1>>>((const int*)ei);
    k_zero<<<(n + 255) / 256, 256>>>(n);
    k_count<<<(e + 255) / 256, 256>>>(ei, e);
    k_scan1<<<nb512, 512>>>(n);
    k_scan2<<<1, 1>>>(nb512);
    k_scan3<<<(n + 255) / 256, 256>>>(n, e);
    k_scatter<<<(e + 255) / 256, 256>>>(ei, e);

    int gb4 = (n + 3) / 4;
    // GCN layer 1: h = relu(gcn(x))
    k_gemm_h<8, 0><<<gb4, 256>>>(x, w1, n);
    k_gcn_agg<<<gb4, 256>>>(b1, n, 0);
    // GCN layer 2: h = h + relu(gcn(h))   (input g_h read in DEVICE code)
    k_gemm_h<64, 1><<<gb4, 256>>>(nullptr, w2, n);
    k_gcn_agg<<<gb4, 256>>>(b2, n, 1);
    // GCN layer 3
    k_gemm_h<64, 1><<<gb4, 256>>>(nullptr, w3, n);
    k_gcn_agg<<<gb4, 256>>>(b3, n, 1);
    // GAT
    k_gat_gemm<<<(n + 7) / 8, 256>>>(wg, att_s, att_d, n);
    k_gat_agg<<<n, 256>>>(bg, n);
    // classifier + log_softmax
    k_classifier<<<gb4, 256>>>(wc1, bc1, wc2, bc2, out, n);
}

// round 4
// speedup vs baseline: 2.2923x; 2.2923x over previous
#include <cuda_runtime.h>
#include <cuda_bf16.h>
#include <math.h>

#define NN 100000
#define EE 1600000
#define HID 64
#define HEADS 4
#define GATD 256

// ---------------- device scratch (no allocations allowed) ----------------
__device__ int   g_is64;
__device__ int   g_count[NN];
__device__ int   g_rowptr[NN + 1];
__device__ int   g_cursor[NN];
__device__ int   g_blocksums[256];
__device__ float g_dinv[NN];
__device__ int   g_esrc[EE];
__device__ float g_enorm[EE];
__device__ float g_hlin[NN * HID];
__device__ float g_h[NN * HID];
__device__ float g_hg[NN * GATD];
__device__ float g_asrc[NN * HEADS];
__device__ float g_adst[NN * HEADS];
__device__ float g_hatt[NN * GATD];

__device__ __forceinline__ int ld_edge(const void* ei, int is64, long long idx) {
    if (is64) return (int)((const long long*)ei)[idx];
    return ((const int*)ei)[idx];
}

// ---------------- dtype detection (int32 vs int64 edge_index) ----------------
__global__ void k_detect(const int* __restrict__ ei) {
    int all0 = 1;
    for (int i = 1; i < 32; i += 2)
        if (ei[i] != 0) { all0 = 0; break; }
    g_is64 = all0;
}

// ---------------- CSR build ----------------
__global__ void k_zero(int n) {
    int i = blockIdx.x * blockDim.x + threadIdx.x;
    if (i < n) g_count[i] = 0;
}

__global__ void k_count(const void* __restrict__ ei, int e) {
    int i = blockIdx.x * blockDim.x + threadIdx.x;
    if (i < e) {
        int is64 = g_is64;
        int d = ld_edge(ei, is64, (long long)e + i);
        atomicAdd(&g_count[d], 1);
    }
}

__global__ void k_scan1(int n) {
    __shared__ int s[512];
    int tid = threadIdx.x;
    int i = blockIdx.x * 512 + tid;
    int v = (i < n) ? g_count[i] : 0;
    s[tid] = v;
    __syncthreads();
    for (int off = 1; off < 512; off <<= 1) {
        int t = (tid >= off) ? s[tid - off] : 0;
        __syncthreads();
        s[tid] += t;
        __syncthreads();
    }
    if (i < n) g_rowptr[i] = s[tid] - v;  // exclusive
    if (tid == 511) g_blocksums[blockIdx.x] = s[511];
}

__global__ void k_scan2(int nb) {
    int run = 0;
    for (int b = 0; b < nb; ++b) {
        int t = g_blocksums[b];
        g_blocksums[b] = run;
        run += t;
    }
}

__global__ void k_scan3(int n, int e) {
    int i = blockIdx.x * blockDim.x + threadIdx.x;
    if (i < n) {
        int rp = g_rowptr[i] + g_blocksums[i >> 9];
        g_rowptr[i] = rp;
        g_cursor[i] = rp;
        g_dinv[i] = rsqrtf((float)(g_count[i] + 1));  // +1 self loop
        if (i == 0) g_rowptr[n] = e;
    }
}

__global__ void k_scatter(const void* __restrict__ ei, int e) {
    int i = blockIdx.x * blockDim.x + threadIdx.x;
    if (i < e) {
        int is64 = g_is64;
        int s = ld_edge(ei, is64, i);
        int d = ld_edge(ei, is64, (long long)e + i);
        int p = atomicAdd(&g_cursor[d], 1);
        g_esrc[p] = s;
        g_enorm[p] = g_dinv[s] * g_dinv[d];
    }
}

// ---------------- layer-1 GEMM: hlin = X[N,8] @ W[8,64] ----------------
__global__ void k_gemm8(const float* __restrict__ X, const float* __restrict__ W, int n) {
    __shared__ float sx[4][8];
    int tid = threadIdx.x;
    int l = tid >> 6, col = tid & 63;
    int base = blockIdx.x * 4;
    if (tid < 32) {
        int r = base + (tid >> 3);
        sx[tid >> 3][tid & 7] = (r < n) ? X[r * 8 + (tid & 7)] : 0.f;
    }
    __syncthreads();
    int node = base + l;
    if (node < n) {
        float acc = 0.f;
#pragma unroll
        for (int k = 0; k < 8; ++k) acc += sx[l][k] * W[k * 64 + col];
        g_hlin[node * 64 + col] = acc;
    }
}

// ---------------- GCN GEMM: hlin = g_h @ W[64,64], W column in registers ----------------
__global__ void __launch_bounds__(256) k_gemm64(const float* __restrict__ W, int n) {
    float w[64];
    int tid = threadIdx.x;
    int l = tid >> 6, col = tid & 63;
#pragma unroll
    for (int k = 0; k < 64; ++k) w[k] = W[k * 64 + col];
    __shared__ float sx[4][64];
    for (int base = blockIdx.x * 4; base < n; base += gridDim.x * 4) {
        __syncthreads();
        int r = base + (tid >> 6);
        sx[tid >> 6][tid & 63] = (r < n) ? g_h[r * 64 + (tid & 63)] : 0.f;
        __syncthreads();
        int node = base + l;
        if (node < n) {
            float acc = 0.f;
#pragma unroll
            for (int k = 0; k < 64; ++k) acc += sx[l][k] * w[k];
            g_hlin[node * 64 + col] = acc;
        }
    }
}

// ---------------- GCN aggregation: warp per node, float2 rows ----------------
__global__ void k_gcn_agg(const float* __restrict__ b, int n, int residual) {
    int tid = threadIdx.x, warp = tid >> 5, lane = tid & 31;
    int node = blockIdx.x * 8 + warp;
    if (node >= n) return;
    const float2* hl = (const float2*)g_hlin;
    float di = g_dinv[node];
    float2 self = hl[node * 32 + lane];
    float accx = di * di * self.x, accy = di * di * self.y;
    int beg = g_rowptr[node], end = g_rowptr[node + 1];
    int j = beg;
    for (; j + 3 < end; j += 4) {
        int s0 = g_esrc[j], s1 = g_esrc[j + 1], s2 = g_esrc[j + 2], s3 = g_esrc[j + 3];
        float w0 = g_enorm[j], w1 = g_enorm[j + 1], w2 = g_enorm[j + 2], w3 = g_enorm[j + 3];
        float2 v0 = hl[s0 * 32 + lane], v1 = hl[s1 * 32 + lane];
        float2 v2 = hl[s2 * 32 + lane], v3 = hl[s3 * 32 + lane];
        accx += w0 * v0.x + w1 * v1.x + w2 * v2.x + w3 * v3.x;
        accy += w0 * v0.y + w1 * v1.y + w2 * v2.y + w3 * v3.y;
    }
    for (; j < end; ++j) {
        int s = g_esrc[j];
        float w = g_enorm[j];
        float2 v = hl[s * 32 + lane];
        accx += w * v.x; accy += w * v.y;
    }
    float2 bb = ((const float2*)b)[lane];
    float vx = fmaxf(accx + bb.x, 0.f), vy = fmaxf(accy + bb.y, 0.f);
    float2* H = (float2*)g_h;
    if (residual) {
        float2 p = H[node * 32 + lane];
        H[node * 32 + lane] = make_float2(p.x + vx, p.y + vy);
    } else {
        H[node * 32 + lane] = make_float2(vx, vy);
    }
}

// ---------------- GAT linear + attention coefficients (wg column in registers) ----------------
__global__ void __launch_bounds__(256) k_gat_gemm(const float* __restrict__ wg,
                                                  const float* __restrict__ att_s,
                                                  const float* __restrict__ att_d, int n) {
    float w[64];
    int tid = threadIdx.x;
    int lane = tid & 31, warp = tid >> 5;
#pragma unroll
    for (int k = 0; k < 64; ++k) w[k] = wg[k * 256 + tid];
    float a_s = att_s[tid], a_d = att_d[tid];
    __shared__ float sh[4][64];
    __shared__ float s_vs[4][8], s_vd[4][8];
    for (int base = blockIdx.x * 4; base < n; base += gridDim.x * 4) {
        __syncthreads();
        int r = base + (tid >> 6);
        sh[tid >> 6][tid & 63] = (r < n) ? g_h[r * 64 + (tid & 63)] : 0.f;
        __syncthreads();
        for (int q = 0; q < 4; ++q) {
            int node = base + q;
            if (node >= n) break;
            float acc = 0.f;
#pragma unroll
            for (int k = 0; k < 64; ++k) acc += sh[q][k] * w[k];
            g_hg[node * 256 + tid] = acc;
            float vs = acc * a_s, vd = acc * a_d;
#pragma unroll
            for (int o = 16; o > 0; o >>= 1) {
                vs += __shfl_xor_sync(0xffffffffu, vs, o);
                vd += __shfl_xor_sync(0xffffffffu, vd, o);
            }
            if (lane == 0) { s_vs[q][warp] = vs; s_vd[q][warp] = vd; }
        }
        __syncthreads();
        if (tid < 16) {
            int q = tid >> 2, h2 = tid & 3;
            int node = base + q;
            if (node < n) {
                g_asrc[node * 4 + h2] = s_vs[q][2 * h2] + s_vs[q][2 * h2 + 1];
                g_adst[node * 4 + h2] = s_vd[q][2 * h2] + s_vd[q][2 * h2 + 1];
            }
        }
    }
}

// ---------------- GAT softmax + aggregation: 4 nodes/block x 64 thr, float4 ----------------
__device__ __forceinline__ float lrelu(float e) { return e > 0.f ? e : 0.2f * e; }

__device__ __forceinline__ float4 wmax4(float4 v) {
#pragma unroll
    for (int o = 16; o > 0; o >>= 1) {
        v.x = fmaxf(v.x, __shfl_xor_sync(0xffffffffu, v.x, o));
        v.y = fmaxf(v.y, __shfl_xor_sync(0xffffffffu, v.y, o));
        v.z = fmaxf(v.z, __shfl_xor_sync(0xffffffffu, v.z, o));
        v.w = fmaxf(v.w, __shfl_xor_sync(0xffffffffu, v.w, o));
    }
    return v;
}

__device__ __forceinline__ float4 wsum4(float4 v) {
#pragma unroll
    for (int o = 16; o > 0; o >>= 1) {
        v.x += __shfl_xor_sync(0xffffffffu, v.x, o);
        v.y += __shfl_xor_sync(0xffffffffu, v.y, o);
        v.z += __shfl_xor_sync(0xffffffffu, v.z, o);
        v.w += __shfl_xor_sync(0xffffffffu, v.w, o);
    }
    return v;
}

__global__ void __launch_bounds__(256) k_gat_agg(const float* __restrict__ bg, int n) {
    int tid = threadIdx.x;
    int g = tid >> 6, t = tid & 63;
    int h = t >> 4;           // head owning my 4 columns
    int wig = (t >> 5) & 1;   // warp within group
    int lane = tid & 31;
    int node = blockIdx.x * 4 + g;
    bool valid = node < n;

    __shared__ float4 s_ex4[4][64];
    __shared__ int    s_srcv[4][64];
    __shared__ float4 s_red[4][2];
    __shared__ int    s_mt[4];

    int beg = 0, m = 0;
    if (valid) { beg = g_rowptr[node]; m = g_rowptr[node + 1] - beg + 1; }
    if (t == 0) s_mt[g] = m;
    __syncthreads();
    int mt = max(max(s_mt[0], s_mt[1]), max(s_mt[2], s_mt[3]));

    float4 ad = valid ? ((const float4*)g_adst)[node] : make_float4(0, 0, 0, 0);

    // pass 1: per-head max of leaky_relu(a_src[s]+a_dst[i])
    float4 mx = make_float4(-1e30f, -1e30f, -1e30f, -1e30f);
    for (int j = t; j < m; j += 64) {
        int s = (j < m - 1) ? g_esrc[beg + j] : node;
        float4 as = ((const float4*)g_asrc)[s];
        mx.x = fmaxf(mx.x, lrelu(as.x + ad.x));
        mx.y = fmaxf(mx.y, lrelu(as.y + ad.y));
        mx.z = fmaxf(mx.z, lrelu(as.z + ad.z));
        mx.w = fmaxf(mx.w, lrelu(as.w + ad.w));
    }
    mx = wmax4(mx);
    if (lane == 0) s_red[g][wig] = mx;
    __syncthreads();
    {
        float4 a = s_red[g][0], b2 = s_red[g][1];
        mx.x = fmaxf(a.x, b2.x); mx.y = fmaxf(a.y, b2.y);
        mx.z = fmaxf(a.z, b2.z); mx.w = fmaxf(a.w, b2.w);
    }

    float4 acc = make_float4(0, 0, 0, 0);
    float4 den = make_float4(0, 0, 0, 0);
    int ntiles = (mt + 63) / 64;
    const float4* hg4 = (const float4*)g_hg;
    const float* s_exf = (const float*)&s_ex4[0][0];
    for (int tile = 0; tile < ntiles; ++tile) {
        __syncthreads();
        int j = tile * 64 + t;
        if (j < m) {
            int s = (j < m - 1) ? g_esrc[beg + j] : node;
            s_srcv[g][t] = s;
            float4 as = ((const float4*)g_asrc)[s];
            float4 ex;
            ex.x = __expf(lrelu(as.x + ad.x) - mx.x);
            ex.y = __expf(lrelu(as.y + ad.y) - mx.y);
            ex.z = __expf(lrelu(as.z + ad.z) - mx.z);
            ex.w = __expf(lrelu(as.w + ad.w) - mx.w);
            den.x += ex.x; den.y += ex.y; den.z += ex.z; den.w += ex.w;
            s_ex4[g][t] = ex;
        }
        __syncthreads();
        int tcnt = min(64, m - tile * 64);
#pragma unroll 4
        for (int jj = 0; jj < tcnt; ++jj) {
            float exv = s_exf[g * 256 + jj * 4 + h];
            float4 v = hg4[(unsigned)s_srcv[g][jj] * 64u + t];
            acc.x += exv * v.x; acc.y += exv * v.y;
            acc.z += exv * v.z; acc.w += exv * v.w;
        }
    }
    den = wsum4(den);
    if (lane == 0) s_red[g][wig] = den;
    __syncthreads();
    float4 d0 = s_red[g][0], d1 = s_red[g][1];
    float4 dt = make_float4(d0.x + d1.x, d0.y + d1.y, d0.z + d1.z, d0.w + d1.w);
    float denh = (h == 0) ? dt.x : (h == 1) ? dt.y : (h == 2) ? dt.z : dt.w;
    if (valid) {
        float4 bgv = ((const float4*)bg)[t];
        float inv = 1.f / (denh + 1e-16f);
        float4 o;
        o.x = acc.x * inv + bgv.x; o.y = acc.y * inv + bgv.y;
        o.z = acc.z * inv + bgv.z; o.w = acc.w * inv + bgv.w;
        ((float4*)g_hatt)[(unsigned)node * 64u + t] = o;
    }
}

// ---------------- classifier: tiled SGEMM (64 nodes x 64 cols, K=256) + logits + log_softmax ----------------
__global__ void __launch_bounds__(256) k_classifier(
    const float* __restrict__ wc1, const float* __restrict__ bc1,
    const float* __restrict__ wc2, const float* __restrict__ bc2,
    float* __restrict__ out, int n) {
    extern __shared__ float sm[];
    float* sW = sm;            // [256][64] = 16384 floats
    float* sA = sm + 16384;    // [64][256] = 16384 floats (reused as sZ [64][65])
    __shared__ float sWc2[192];
    __shared__ float sB[64];
    __shared__ float sB2[3];
    __shared__ float sLg[192];
    __shared__ float sLse[64];

    int tid = threadIdx.x;
    int base = blockIdx.x * 64;

    for (int i = tid; i < 4096; i += 256) ((float4*)sW)[i] = ((const float4*)wc1)[i];
    if (tid < 192) sWc2[tid] = wc2[tid];
    if (tid < 64) sB[tid] = bc1[tid];
    if (tid < 3) sB2[tid] = bc2[tid];

    // load A tile [64 nodes][256 feats] row-major (zero-fill tail rows)
    const float4* hatt4 = (const float4*)g_hatt;
    for (int i = tid; i < 4096; i += 256) {
        int r = i >> 6;
        float4 v = make_float4(0, 0, 0, 0);
        if (base + r < n) v = hatt4[(unsigned)(base + r) * 64u + (i & 63)];
        ((float4*)sA)[i] = v;
    }
    __syncthreads();

    int colq = tid & 15;   // cols 4*colq .. +3
    int nodeq = tid >> 4;  // rows 4*nodeq .. +3
    float az[4][4];
#pragma unroll
    for (int i = 0; i < 4; ++i)
#pragma unroll
        for (int c = 0; c < 4; ++c) az[i][c] = 0.f;

    const float4* sW4 = (const float4*)sW;
#pragma unroll 4
    for (int k = 0; k < 256; ++k) {
        float a0 = sA[(nodeq * 4 + 0) * 256 + k];
        float a1 = sA[(nodeq * 4 + 1) * 256 + k];
        float a2 = sA[(nodeq * 4 + 2) * 256 + k];
        float a3 = sA[(nodeq * 4 + 3) * 256 + k];
        float4 wv = sW4[k * 16 + colq];
        az[0][0] += a0 * wv.x; az[0][1] += a0 * wv.y; az[0][2] += a0 * wv.z; az[0][3] += a0 * wv.w;
        az[1][0] += a1 * wv.x; az[1][1] += a1 * wv.y; az[1][2] += a1 * wv.z; az[1][3] += a1 * wv.w;
        az[2][0] += a2 * wv.x; az[2][1] += a2 * wv.y; az[2][2] += a2 * wv.z; az[2][3] += a2 * wv.w;
        az[3][0] += a3 * wv.x; az[3][1] += a3 * wv.y; az[3][2] += a3 * wv.z; az[3][3] += a3 * wv.w;
    }
    __syncthreads();  // done reading sA; reuse as sZ
    float* sZ = sA;   // [64][65]
#pragma unroll
    for (int i = 0; i < 4; ++i)
#pragma unroll
        for (int c = 0; c < 4; ++c)
            sZ[(nodeq * 4 + i) * 65 + colq * 4 + c] = fmaxf(az[i][c] + sB[colq * 4 + c], 0.f);
    __syncthreads();

    if (tid < 192) {
        int r = tid / 3, o = tid - 3 * r;
        float a = sB2[o];
#pragma unroll 8
        for (int c = 0; c < 64; ++c) a += sZ[r * 65 + c] * sWc2[c * 3 + o];
        sLg[tid] = a;
    }
    __syncthreads();
    if (tid < 64) {
        float l0 = sLg[tid * 3 + 0], l1 = sLg[tid * 3 + 1], l2 = sLg[tid * 3 + 2];
        float mm = fmaxf(l0, fmaxf(l1, l2));
        sLse[tid] = mm + logf(__expf(l0 - mm) + __expf(l1 - mm) + __expf(l2 - mm));
    }
    __syncthreads();
    int nvalid = n - base; if (nvalid > 64) nvalid = 64;
    if (tid < nvalid * 3) out[base * 3 + tid] = sLg[tid] - sLse[tid / 3];
}

// ---------------- launch ----------------
extern "C" void kernel_launch(void* const* d_in, const int* in_sizes, int n_in,
                              void* d_out, int out_size) {
    const float* x     = (const float*)d_in[0];
    const void*  ei    = (const void*)d_in[1];
    const float* w1    = (const float*)d_in[2];
    const float* b1    = (const float*)d_in[3];
    const float* w2    = (const float*)d_in[4];
    const float* b2    = (const float*)d_in[5];
    const float* w3    = (const float*)d_in[6];
    const float* b3    = (const float*)d_in[7];
    const float* wg    = (const float*)d_in[8];
    const float* bg    = (const float*)d_in[9];
    const float* att_s = (const float*)d_in[10];
    const float* att_d = (const float*)d_in[11];
    const float* wc1   = (const float*)d_in[12];
    const float* bc1   = (const float*)d_in[13];
    const float* wc2   = (const float*)d_in[14];
    const float* bc2   = (const float*)d_in[15];
    float* out = (float*)d_out;

    int n = in_sizes[0] / 8;
    int e = in_sizes[1] / 2;

    int nb512 = (n + 511) / 512;

    k_detect<<<1, 1>>>((const int*)ei);
    k_zero<<<(n + 255) / 256, 256>>>(n);
    k_count<<<(e + 255) / 256, 256>>>(ei, e);
    k_scan1<<<nb512, 512>>>(n);
    k_scan2<<<1, 1>>>(nb512);
    k_scan3<<<(n + 255) / 256, 256>>>(n, e);
    k_scatter<<<(e + 255) / 256, 256>>>(ei, e);

    int gb4 = (n + 3) / 4;
    int gs = 444;  // 3 blocks/SM x 148 SMs for register-heavy grid-stride kernels

    // GCN layer 1
    k_gemm8<<<gb4, 256>>>(x, w1, n);
    k_gcn_agg<<<(n + 7) / 8, 256>>>(b1, n, 0);
    // GCN layer 2 (residual)
    k_gemm64<<<gs, 256>>>(w2, n);
    k_gcn_agg<<<(n + 7) / 8, 256>>>(b2, n, 1);
    // GCN layer 3 (residual)
    k_gemm64<<<gs, 256>>>(w3, n);
    k_gcn_agg<<<(n + 7) / 8, 256>>>(b3, n, 1);
    // GAT
    k_gat_gemm<<<gs, 256>>>(wg, att_s, att_d, n);
    k_gat_agg<<<gb4, 256>>>(bg, n);
    // classifier (132 KB dynamic smem)
    static int smem_set = 0;
    if (!smem_set) {
        cudaFuncSetAttribute(k_classifier, cudaFuncAttributeMaxDynamicSharedMemorySize, 135168);
        smem_set = 1;
    }
    k_classifier<<<(n + 63) / 64, 256, 32768 * 4>>>(wc1, bc1, wc2, bc2, out, n);
}

// round 7
// speedup vs baseline: 2.4852x; 1.0841x over previous
#include <cuda_runtime.h>
#include <cuda_bf16.h>
#include <math.h>

#define NN 100000
#define EE 1600000
#define HID 64
#define HEADS 4
#define GATD 256

// ---------------- device scratch (no allocations allowed) ----------------
__device__ int   g_is64;
__device__ int   g_count[NN];
__device__ int   g_rowptr[NN + 1];
__device__ int   g_cursor[NN];
__device__ int   g_blocksums[256];
__device__ float g_dinv[NN];
__device__ int   g_esrc[EE];
__device__ float g_enorm[EE];
__device__ float g_hlin[NN * HID];
__device__ float g_h[NN * HID];
__device__ __nv_bfloat16 g_hg_bf[NN * GATD];   // bf16 value matrix: 51MB -> L2-resident
__device__ float g_asrc[NN * HEADS];
__device__ float g_adst[NN * HEADS];
__device__ float g_hatt[NN * GATD];

__device__ __forceinline__ int ld_edge(const void* ei, int is64, long long idx) {
    if (is64) return (int)((const long long*)ei)[idx];
    return ((const int*)ei)[idx];
}

// ---------------- dtype detection (int32 vs int64 edge_index) ----------------
__global__ void k_detect(const int* __restrict__ ei) {
    int all0 = 1;
    for (int i = 1; i < 32; i += 2)
        if (ei[i] != 0) { all0 = 0; break; }
    g_is64 = all0;
}

// ---------------- CSR build ----------------
__global__ void k_zero(int n) {
    int i = blockIdx.x * blockDim.x + threadIdx.x;
    if (i < n) g_count[i] = 0;
}

__global__ void k_count(const void* __restrict__ ei, int e) {
    int i = blockIdx.x * blockDim.x + threadIdx.x;
    if (i < e) {
        int is64 = g_is64;
        int d = ld_edge(ei, is64, (long long)e + i);
        atomicAdd(&g_count[d], 1);
    }
}

__global__ void k_scan1(int n) {
    __shared__ int s[512];
    int tid = threadIdx.x;
    int i = blockIdx.x * 512 + tid;
    int v = (i < n) ? g_count[i] : 0;
    s[tid] = v;
    __syncthreads();
    for (int off = 1; off < 512; off <<= 1) {
        int t = (tid >= off) ? s[tid - off] : 0;
        __syncthreads();
        s[tid] += t;
        __syncthreads();
    }
    if (i < n) g_rowptr[i] = s[tid] - v;  // exclusive
    if (tid == 511) g_blocksums[blockIdx.x] = s[511];
}

__global__ void k_scan2(int nb) {
    int run = 0;
    for (int b = 0; b < nb; ++b) {
        int t = g_blocksums[b];
        g_blocksums[b] = run;
        run += t;
    }
}

__global__ void k_scan3(int n, int e) {
    int i = blockIdx.x * blockDim.x + threadIdx.x;
    if (i < n) {
        int rp = g_rowptr[i] + g_blocksums[i >> 9];
        g_rowptr[i] = rp;
        g_cursor[i] = rp;
        g_dinv[i] = rsqrtf((float)(g_count[i] + 1));  // +1 self loop
        if (i == 0) g_rowptr[n] = e;
    }
}

__global__ void k_scatter(const void* __restrict__ ei, int e) {
    int i = blockIdx.x * blockDim.x + threadIdx.x;
    if (i < e) {
        int is64 = g_is64;
        int s = ld_edge(ei, is64, i);
        int d = ld_edge(ei, is64, (long long)e + i);
        int p = atomicAdd(&g_cursor[d], 1);
        g_esrc[p] = s;
        g_enorm[p] = g_dinv[s] * g_dinv[d];
    }
}

// ---------------- layer-1 GEMM: hlin = X[N,8] @ W[8,64] ----------------
__global__ void k_gemm8(const float* __restrict__ X, const float* __restrict__ W, int n) {
    __shared__ float sx[4][8];
    int tid = threadIdx.x;
    int l = tid >> 6, col = tid & 63;
    int base = blockIdx.x * 4;
    if (tid < 32) {
        int r = base + (tid >> 3);
        sx[tid >> 3][tid & 7] = (r < n) ? X[r * 8 + (tid & 7)] : 0.f;
    }
    __syncthreads();
    int node = base + l;
    if (node < n) {
        float acc = 0.f;
#pragma unroll
        for (int k = 0; k < 8; ++k) acc += sx[l][k] * W[k * 64 + col];
        g_hlin[node * 64 + col] = acc;
    }
}

// ---------------- GCN GEMM: hlin = g_h @ W[64,64], W column in registers ----------------
__global__ void __launch_bounds__(256) k_gemm64(const float* __restrict__ W, int n) {
    float w[64];
    int tid = threadIdx.x;
    int l = tid >> 6, col = tid & 63;
#pragma unroll
    for (int k = 0; k < 64; ++k) w[k] = W[k * 64 + col];
    __shared__ float sx[4][64];
    for (int base = blockIdx.x * 4; base < n; base += gridDim.x * 4) {
        __syncthreads();
        int r = base + (tid >> 6);
        sx[tid >> 6][tid & 63] = (r < n) ? g_h[r * 64 + (tid & 63)] : 0.f;
        __syncthreads();
        int node = base + l;
        if (node < n) {
            float acc = 0.f;
#pragma unroll
            for (int k = 0; k < 64; ++k) acc += sx[l][k] * w[k];
            g_hlin[node * 64 + col] = acc;
        }
    }
}

// ---------------- GCN aggregation: warp per node, float2 rows ----------------
__global__ void k_gcn_agg(const float* __restrict__ b, int n, int residual) {
    int tid = threadIdx.x, warp = tid >> 5, lane = tid & 31;
    int node = blockIdx.x * 8 + warp;
    if (node >= n) return;
    const float2* hl = (const float2*)g_hlin;
    float di = g_dinv[node];
    float2 self = hl[node * 32 + lane];
    float accx = di * di * self.x, accy = di * di * self.y;
    int beg = g_rowptr[node], end = g_rowptr[node + 1];
    int j = beg;
    for (; j + 3 < end; j += 4) {
        int s0 = g_esrc[j], s1 = g_esrc[j + 1], s2 = g_esrc[j + 2], s3 = g_esrc[j + 3];
        float w0 = g_enorm[j], w1 = g_enorm[j + 1], w2 = g_enorm[j + 2], w3 = g_enorm[j + 3];
        float2 v0 = hl[s0 * 32 + lane], v1 = hl[s1 * 32 + lane];
        float2 v2 = hl[s2 * 32 + lane], v3 = hl[s3 * 32 + lane];
        accx += w0 * v0.x + w1 * v1.x + w2 * v2.x + w3 * v3.x;
        accy += w0 * v0.y + w1 * v1.y + w2 * v2.y + w3 * v3.y;
    }
    for (; j < end; ++j) {
        int s = g_esrc[j];
        float w = g_enorm[j];
        float2 v = hl[s * 32 + lane];
        accx += w * v.x; accy += w * v.y;
    }
    float2 bb = ((const float2*)b)[lane];
    float vx = fmaxf(accx + bb.x, 0.f), vy = fmaxf(accy + bb.y, 0.f);
    float2* H = (float2*)g_h;
    if (residual) {
        float2 p = H[node * 32 + lane];
        H[node * 32 + lane] = make_float2(p.x + vx, p.y + vy);
    } else {
        H[node * 32 + lane] = make_float2(vx, vy);
    }
}

// ---------------- GAT linear + attention coefficients (wg column in registers) ----------------
__global__ void __launch_bounds__(256) k_gat_gemm(const float* __restrict__ wg,
                                                  const float* __restrict__ att_s,
                                                  const float* __restrict__ att_d, int n) {
    float w[64];
    int tid = threadIdx.x;
    int lane = tid & 31, warp = tid >> 5;
#pragma unroll
    for (int k = 0; k < 64; ++k) w[k] = wg[k * 256 + tid];
    float a_s = att_s[tid], a_d = att_d[tid];
    __shared__ float sh[4][64];
    __shared__ float s_vs[4][8], s_vd[4][8];
    for (int base = blockIdx.x * 4; base < n; base += gridDim.x * 4) {
        __syncthreads();
        int r = base + (tid >> 6);
        sh[tid >> 6][tid & 63] = (r < n) ? g_h[r * 64 + (tid & 63)] : 0.f;
        __syncthreads();
        for (int q = 0; q < 4; ++q) {
            int node = base + q;
            if (node >= n) break;
            float acc = 0.f;
#pragma unroll
            for (int k = 0; k < 64; ++k) acc += sh[q][k] * w[k];
            g_hg_bf[node * 256 + tid] = __float2bfloat16(acc);  // bf16 value matrix
            float vs = acc * a_s, vd = acc * a_d;                // logits stay fp32
#pragma unroll
            for (int o = 16; o > 0; o >>= 1) {
                vs += __shfl_xor_sync(0xffffffffu, vs, o);
                vd += __shfl_xor_sync(0xffffffffu, vd, o);
            }
            if (lane == 0) { s_vs[q][warp] = vs; s_vd[q][warp] = vd; }
        }
        __syncthreads();
        if (tid < 16) {
            int q = tid >> 2, h2 = tid & 3;
            int node = base + q;
            if (node < n) {
                g_asrc[node * 4 + h2] = s_vs[q][2 * h2] + s_vs[q][2 * h2 + 1];
                g_adst[node * 4 + h2] = s_vd[q][2 * h2] + s_vd[q][2 * h2 + 1];
            }
        }
    }
}

// ---------------- GAT softmax + aggregation: 4 nodes/block x 64 thr, bf16 gathers ----------------
__device__ __forceinline__ float lrelu(float e) { return e > 0.f ? e : 0.2f * e; }

__device__ __forceinline__ float4 wmax4(float4 v) {
#pragma unroll
    for (int o = 16; o > 0; o >>= 1) {
        v.x = fmaxf(v.x, __shfl_xor_sync(0xffffffffu, v.x, o));
        v.y = fmaxf(v.y, __shfl_xor_sync(0xffffffffu, v.y, o));
        v.z = fmaxf(v.z, __shfl_xor_sync(0xffffffffu, v.z, o));
        v.w = fmaxf(v.w, __shfl_xor_sync(0xffffffffu, v.w, o));
    }
    return v;
}

__device__ __forceinline__ float4 wsum4(float4 v) {
#pragma unroll
    for (int o = 16; o > 0; o >>= 1) {
        v.x += __shfl_xor_sync(0xffffffffu, v.x, o);
        v.y += __shfl_xor_sync(0xffffffffu, v.y, o);
        v.z += __shfl_xor_sync(0xffffffffu, v.z, o);
        v.w += __shfl_xor_sync(0xffffffffu, v.w, o);
    }
    return v;
}

__global__ void __launch_bounds__(256) k_gat_agg(const float* __restrict__ bg, int n) {
    int tid = threadIdx.x;
    int g = tid >> 6, t = tid & 63;
    int h = t >> 4;           // head owning my 4 columns
    int wig = (t >> 5) & 1;   // warp within group
    int lane = tid & 31;
    int node = blockIdx.x * 4 + g;
    bool valid = node < n;

    __shared__ float4 s_ex4[4][64];
    __shared__ int    s_srcv[4][64];
    __shared__ float4 s_red[4][2];

    int beg = 0, m = 0;
    if (valid) { beg = g_rowptr[node]; m = g_rowptr[node + 1] - beg + 1; }

    float4 ad = valid ? ((const float4*)g_adst)[node] : make_float4(0, 0, 0, 0);

    // pass 1: per-head max of leaky_relu(a_src[s]+a_dst[i])
    float4 mx = make_float4(-1e30f, -1e30f, -1e30f, -1e30f);
    for (int j = t; j < m; j += 64) {
        int s = (j < m - 1) ? g_esrc[beg + j] : node;
        float4 as = ((const float4*)g_asrc)[s];
        mx.x = fmaxf(mx.x, lrelu(as.x + ad.x));
        mx.y = fmaxf(mx.y, lrelu(as.y + ad.y));
        mx.z = fmaxf(mx.z, lrelu(as.z + ad.z));
        mx.w = fmaxf(mx.w, lrelu(as.w + ad.w));
    }
    mx = wmax4(mx);
    if (lane == 0) s_red[g][wig] = mx;
    __syncthreads();
    {
        float4 a = s_red[g][0], b2 = s_red[g][1];
        mx.x = fmaxf(a.x, b2.x); mx.y = fmaxf(a.y, b2.y);
        mx.z = fmaxf(a.z, b2.z); mx.w = fmaxf(a.w, b2.w);
    }

    float4 acc = make_float4(0, 0, 0, 0);
    float4 den = make_float4(0, 0, 0, 0);
    int ntiles = (m + 63) / 64;
    // block-uniform tile count (groups may have different m)
    __shared__ int s_nt[4];
    if (t == 0) s_nt[g] = ntiles;
    __syncthreads();
    int ntmax = max(max(s_nt[0], s_nt[1]), max(s_nt[2], s_nt[3]));

    const uint2* hgq = (const uint2*)g_hg_bf;  // 8B = 4 bf16 per thread
    const float* s_exf = (const float*)&s_ex4[0][0];
    for (int tile = 0; tile < ntmax; ++tile) {
        __syncthreads();
        int j = tile * 64 + t;
        if (j < m) {
            int s = (j < m - 1) ? g_esrc[beg + j] : node;
            s_srcv[g][t] = s;
            float4 as = ((const float4*)g_asrc)[s];
            float4 ex;
            ex.x = __expf(lrelu(as.x + ad.x) - mx.x);
            ex.y = __expf(lrelu(as.y + ad.y) - mx.y);
            ex.z = __expf(lrelu(as.z + ad.z) - mx.z);
            ex.w = __expf(lrelu(as.w + ad.w) - mx.w);
            den.x += ex.x; den.y += ex.y; den.z += ex.z; den.w += ex.w;
            s_ex4[g][t] = ex;
        }
        __syncthreads();
        int tcnt = min(64, m - tile * 64);
#pragma unroll 4
        for (int jj = 0; jj < tcnt; ++jj) {
            float exv = s_exf[g * 256 + jj * 4 + h];
            uint2 raw = hgq[(unsigned)s_srcv[g][jj] * 64u + t];
            float2 f0 = __bfloat1622float2(*(const __nv_bfloat162*)&raw.x);
            float2 f1 = __bfloat1622float2(*(const __nv_bfloat162*)&raw.y);
            acc.x += exv * f0.x; acc.y += exv * f0.y;
            acc.z += exv * f1.x; acc.w += exv * f1.y;
        }
    }
    den = wsum4(den);
    if (lane == 0) s_red[g][wig] = den;
    __syncthreads();
    float4 d0 = s_red[g][0], d1 = s_red[g][1];
    float4 dt = make_float4(d0.x + d1.x, d0.y + d1.y, d0.z + d1.z, d0.w + d1.w);
    float denh = (h == 0) ? dt.x : (h == 1) ? dt.y : (h == 2) ? dt.z : dt.w;
    if (valid) {
        float4 bgv = ((const float4*)bg)[t];
        float inv = 1.f / (denh + 1e-16f);
        float4 o;
        o.x = acc.x * inv + bgv.x; o.y = acc.y * inv + bgv.y;
        o.z = acc.z * inv + bgv.z; o.w = acc.w * inv + bgv.w;
        ((float4*)g_hatt)[(unsigned)node * 64u + t] = o;
    }
}

// ---------------- classifier: tiled SGEMM (64 nodes x 64 cols, K=256) + logits + log_softmax ----------------
__global__ void __launch_bounds__(256) k_classifier(
    const float* __restrict__ wc1, const float* __restrict__ bc1,
    const float* __restrict__ wc2, const float* __restrict__ bc2,
    float* __restrict__ out, int n) {
    extern __shared__ float sm[];
    float* sW = sm;            // [256][64] = 16384 floats
    float* sA = sm + 16384;    // [64][256] = 16384 floats (reused as sZ [64][65])
    __shared__ float sWc2[192];
    __shared__ float sB[64];
    __shared__ float sB2[3];
    __shared__ float sLg[192];
    __shared__ float sLse[64];

    int tid = threadIdx.x;
    int base = blockIdx.x * 64;

    for (int i = tid; i < 4096; i += 256) ((float4*)sW)[i] = ((const float4*)wc1)[i];
    if (tid < 192) sWc2[tid] = wc2[tid];
    if (tid < 64) sB[tid] = bc1[tid];
    if (tid < 3) sB2[tid] = bc2[tid];

    const float4* hatt4 = (const float4*)g_hatt;
    for (int i = tid; i < 4096; i += 256) {
        int r = i >> 6;
        float4 v = make_float4(0, 0, 0, 0);
        if (base + r < n) v = hatt4[(unsigned)(base + r) * 64u + (i & 63)];
        ((float4*)sA)[i] = v;
    }
    __syncthreads();

    int colq = tid & 15;
    int nodeq = tid >> 4;
    float az[4][4];
#pragma unroll
    for (int i = 0; i < 4; ++i)
#pragma unroll
        for (int c = 0; c < 4; ++c) az[i][c] = 0.f;

    const float4* sW4 = (const float4*)sW;
#pragma unroll 4
    for (int k = 0; k < 256; ++k) {
        float a0 = sA[(nodeq * 4 + 0) * 256 + k];
        float a1 = sA[(nodeq * 4 + 1) * 256 + k];
        float a2 = sA[(nodeq * 4 + 2) * 256 + k];
        float a3 = sA[(nodeq * 4 + 3) * 256 + k];
        float4 wv = sW4[k * 16 + colq];
        az[0][0] += a0 * wv.x; az[0][1] += a0 * wv.y; az[0][2] += a0 * wv.z; az[0][3] += a0 * wv.w;
        az[1][0] += a1 * wv.x; az[1][1] += a1 * wv.y; az[1][2] += a1 * wv.z; az[1][3] += a1 * wv.w;
        az[2][0] += a2 * wv.x; az[2][1] += a2 * wv.y; az[2][2] += a2 * wv.z; az[2][3] += a2 * wv.w;
        az[3][0] += a3 * wv.x; az[3][1] += a3 * wv.y; az[3][2] += a3 * wv.z; az[3][3] += a3 * wv.w;
    }
    __syncthreads();
    float* sZ = sA;
#pragma unroll
    for (int i = 0; i < 4; ++i)
#pragma unroll
        for (int c = 0; c < 4; ++c)
            sZ[(nodeq * 4 + i) * 65 + colq * 4 + c] = fmaxf(az[i][c] + sB[colq * 4 + c], 0.f);
    __syncthreads();

    if (tid < 192) {
        int r = tid / 3, o = tid - 3 * r;
        float a = sB2[o];
#pragma unroll 8
        for (int c = 0; c < 64; ++c) a += sZ[r * 65 + c] * sWc2[c * 3 + o];
        sLg[tid] = a;
    }
    __syncthreads();
    if (tid < 64) {
        float l0 = sLg[tid * 3 + 0], l1 = sLg[tid * 3 + 1], l2 = sLg[tid * 3 + 2];
        float mm = fmaxf(l0, fmaxf(l1, l2));
        sLse[tid] = mm + logf(__expf(l0 - mm) + __expf(l1 - mm) + __expf(l2 - mm));
    }
    __syncthreads();
    int nvalid = n - base; if (nvalid > 64) nvalid = 64;
    if (tid < nvalid * 3) out[base * 3 + tid] = sLg[tid] - sLse[tid / 3];
}

// ---------------- launch ----------------
extern "C" void kernel_launch(void* const* d_in, const int* in_sizes, int n_in,
                              void* d_out, int out_size) {
    const float* x     = (const float*)d_in[0];
    const void*  ei    = (const void*)d_in[1];
    const float* w1    = (const float*)d_in[2];
    const float* b1    = (const float*)d_in[3];
    const float* w2    = (const float*)d_in[4];
    const float* b2    = (const float*)d_in[5];
    const float* w3    = (const float*)d_in[6];
    const float* b3    = (const float*)d_in[7];
    const float* wg    = (const float*)d_in[8];
    const float* bg    = (const float*)d_in[9];
    const float* att_s = (const float*)d_in[10];
    const float* att_d = (const float*)d_in[11];
    const float* wc1   = (const float*)d_in[12];
    const float* bc1   = (const float*)d_in[13];
    const float* wc2   = (const float*)d_in[14];
    const float* bc2   = (const float*)d_in[15];
    float* out = (float*)d_out;

    int n = in_sizes[0] / 8;
    int e = in_sizes[1] / 2;

    int nb512 = (n + 511) / 512;

    k_detect<<<1, 1>>>((const int*)ei);
    k_zero<<<(n + 255) / 256, 256>>>(n);
    k_count<<<(e + 255) / 256, 256>>>(ei, e);
    k_scan1<<<nb512, 512>>>(n);
    k_scan2<<<1, 1>>>(nb512);
    k_scan3<<<(n + 255) / 256, 256>>>(n, e);
    k_scatter<<<(e + 255) / 256, 256>>>(ei, e);

    int gb4 = (n + 3) / 4;
    int gs = 444;

    k_gemm8<<<gb4, 256>>>(x, w1, n);
    k_gcn_agg<<<(n + 7) / 8, 256>>>(b1, n, 0);
    k_gemm64<<<gs, 256>>>(w2, n);
    k_gcn_agg<<<(n + 7) / 8, 256>>>(b2, n, 1);
    k_gemm64<<<gs, 256>>>(w3, n);
    k_gcn_agg<<<(n + 7) / 8, 256>>>(b3, n, 1);
    k_gat_gemm<<<gs, 256>>>(wg, att_s, att_d, n);
    k_gat_agg<<<gb4, 256>>>(bg, n);
    static int smem_set = 0;
    if (!smem_set) {
        cudaFuncSetAttribute(k_classifier, cudaFuncAttributeMaxDynamicSharedMemorySize, 135168);
        smem_set = 1;
    }
    k_classifier<<<(n + 63) / 64, 256, 32768 * 4>>>(wc1, bc1, wc2, bc2, out, n);
}